// round 1
// baseline (speedup 1.0000x reference)
#include <cuda_runtime.h>
#include <math.h>

// Problem constants
#define Bb 64
#define Tt 21
#define Ee 512
#define Hh 512
#define Vv 10000
#define G4 2048   // 4*H
#define Kk 512

// Scratch (static device allocations; no cudaMalloc allowed)
__device__ float d_X[Tt * Bb * Ee];        // gathered inputs, row m = t*64+b
__device__ float d_gpre[Tt * Bb * G4];     // x@W_ih^T + b_ih + b_hh per timestep
__device__ float d_gates[Bb * G4];         // per-step gate buffer
__device__ float d_h[Bb * Hh];
__device__ float d_c[Bb * Hh];
__device__ float d_hall[(Tt - 1) * Bb * Hh]; // row m = b*20 + s  (matches out layout)

// Gather features (t=0) and caption_embedding[:, t-1] (t=1..20) into X[1344,512]
__global__ void build_x(const float* __restrict__ feat, const float* __restrict__ emb) {
    int idx = blockIdx.x * blockDim.x + threadIdx.x;
    if (idx >= Tt * Bb * Ee) return;
    int k = idx % Ee;
    int m = idx / Ee;
    int b = m % Bb;
    int t = m / Bb;
    float v = (t == 0) ? feat[b * Ee + k]
                       : emb[(b * Tt + (t - 1)) * Ee + k];
    d_X[idx] = v;
}

// C[M,N] = A[M,K] * B[N,K]^T (+bias1[col]) (+bias2[col]) (+addm[row,col])
// A row-major ld=K, B row-major ld=K (NT layout: dot along contiguous K).
// Requires M % BM == 0, K % BK == 0. N guarded.
template <int BM, int BN, int BK, int TM, int TN>
__global__ void gemm_nt(const float* __restrict__ A, const float* __restrict__ Bm,
                        const float* __restrict__ addm,
                        const float* __restrict__ bias1, const float* __restrict__ bias2,
                        float* __restrict__ C, int M, int N, int K) {
    constexpr int THREADS = (BM / TM) * (BN / TN);
    __shared__ float As[BK][BM + 4];
    __shared__ float Bs[BK][BN + 4];

    const int tid = threadIdx.x;
    const int tx = tid % (BN / TN);
    const int ty = tid / (BN / TN);
    const int rowBase = blockIdx.y * BM;
    const int colBase = blockIdx.x * BN;

    float acc[TM][TN];
#pragma unroll
    for (int i = 0; i < TM; ++i)
#pragma unroll
        for (int j = 0; j < TN; ++j) acc[i][j] = 0.0f;

    for (int k0 = 0; k0 < K; k0 += BK) {
        // Load A tile BM x BK (always in-bounds: M % BM == 0)
        for (int v = tid; v < BM * BK / 4; v += THREADS) {
            int r = v / (BK / 4);
            int c4 = v % (BK / 4);
            float4 val = *reinterpret_cast<const float4*>(
                &A[(size_t)(rowBase + r) * K + k0 + c4 * 4]);
            As[c4 * 4 + 0][r] = val.x;
            As[c4 * 4 + 1][r] = val.y;
            As[c4 * 4 + 2][r] = val.z;
            As[c4 * 4 + 3][r] = val.w;
        }
        // Load B tile BN x BK (guard N)
        for (int v = tid; v < BN * BK / 4; v += THREADS) {
            int r = v / (BK / 4);
            int c4 = v % (BK / 4);
            int n = colBase + r;
            float4 val = make_float4(0.f, 0.f, 0.f, 0.f);
            if (n < N)
                val = *reinterpret_cast<const float4*>(
                    &Bm[(size_t)n * K + k0 + c4 * 4]);
            Bs[c4 * 4 + 0][r] = val.x;
            Bs[c4 * 4 + 1][r] = val.y;
            Bs[c4 * 4 + 2][r] = val.z;
            Bs[c4 * 4 + 3][r] = val.w;
        }
        __syncthreads();

#pragma unroll
        for (int k = 0; k < BK; ++k) {
            float a[TM], b[TN];
#pragma unroll
            for (int i = 0; i < TM; ++i) a[i] = As[k][ty * TM + i];
#pragma unroll
            for (int j = 0; j < TN; ++j) b[j] = Bs[k][tx * TN + j];
#pragma unroll
            for (int i = 0; i < TM; ++i)
#pragma unroll
                for (int j = 0; j < TN; ++j) acc[i][j] += a[i] * b[j];
        }
        __syncthreads();
    }

    // Epilogue
#pragma unroll
    for (int i = 0; i < TM; ++i) {
        int row = rowBase + ty * TM + i;
#pragma unroll
        for (int j = 0; j < TN; ++j) {
            int col = colBase + tx * TN + j;
            if (col < N) {
                float v = acc[i][j];
                if (bias1) v += bias1[col];
                if (bias2) v += bias2[col];
                if (addm) v += addm[(size_t)row * N + col];
                C[(size_t)row * N + col] = v;
            }
        }
    }
}

// LSTM gate nonlinearity + state update. PyTorch gate order i,f,g,o.
__global__ void lstm_elem(const float* __restrict__ gates, float* __restrict__ h,
                          float* __restrict__ c, float* __restrict__ hall,
                          int s, int first) {
    int idx = blockIdx.x * blockDim.x + threadIdx.x;
    if (idx >= Bb * Hh) return;
    int b = idx / Hh;
    int k = idx % Hh;
    const float* g = gates + (size_t)b * G4;
    float gi = g[k];
    float gf = g[Hh + k];
    float gg = g[2 * Hh + k];
    float go = g[3 * Hh + k];
    float i_ = 1.0f / (1.0f + expf(-gi));
    float f_ = 1.0f / (1.0f + expf(-gf));
    float g_ = tanhf(gg);
    float o_ = 1.0f / (1.0f + expf(-go));
    float cp = first ? 0.0f : c[idx];
    float cn = f_ * cp + i_ * g_;
    c[idx] = cn;
    float hn = o_ * tanhf(cn);
    h[idx] = hn;
    if (s >= 0) hall[((size_t)b * (Tt - 1) + s) * Hh + k] = hn;
}

extern "C" void kernel_launch(void* const* d_in, const int* in_sizes, int n_in,
                              void* d_out, int out_size) {
    const float* feat  = (const float*)d_in[0];
    const float* emb   = (const float*)d_in[1];
    const float* W_ih  = (const float*)d_in[2];
    const float* W_hh  = (const float*)d_in[3];
    const float* b_ih  = (const float*)d_in[4];
    const float* b_hh  = (const float*)d_in[5];
    const float* W_lin = (const float*)d_in[6];
    const float* b_lin = (const float*)d_in[7];
    float* out = (float*)d_out;

    float *X, *gpre, *gates, *h, *c, *hall;
    cudaGetSymbolAddress((void**)&X, d_X);
    cudaGetSymbolAddress((void**)&gpre, d_gpre);
    cudaGetSymbolAddress((void**)&gates, d_gates);
    cudaGetSymbolAddress((void**)&h, d_h);
    cudaGetSymbolAddress((void**)&c, d_c);
    cudaGetSymbolAddress((void**)&hall, d_hall);

    // 1) Gather inputs for all timesteps
    int nb = (Tt * Bb * Ee + 255) / 256;
    build_x<<<nb, 256>>>(feat, emb);

    // 2) Precompute x@W_ih^T + (b_ih+b_hh) for all 21 steps in one GEMM
    {
        dim3 grid(G4 / 64, (Tt * Bb) / 64);  // 32 x 21
        gemm_nt<64, 64, 32, 4, 4><<<grid, 256>>>(
            X, W_ih, nullptr, b_ih, b_hh, gpre, Tt * Bb, G4, Kk);
    }

    // 3) t = 0: h,c = 0, so gates == gpre[0]; no output emitted
    int ne = (Bb * Hh + 255) / 256;
    lstm_elem<<<ne, 256>>>(gpre, h, c, hall, -1, 1);

    // 4) t = 1..20: gates = gpre[t] + h@W_hh^T, then state update + store h
    for (int t = 1; t < Tt; ++t) {
        dim3 grid(G4 / 64, Bb / 16);  // 32 x 4 = 128 CTAs
        gemm_nt<16, 64, 32, 1, 4><<<grid, 256>>>(
            h, W_hh, gpre + (size_t)t * Bb * G4, nullptr, nullptr,
            gates, Bb, G4, Kk);
        lstm_elem<<<ne, 256>>>(gates, h, c, hall, t - 1, 0);
    }

    // 5) One big projection GEMM: out[1280,10000] = hall @ W_lin^T + b_lin
    //    hall rows are (b*20+s), which is exactly d_out's [B,20,V] row order.
    {
        dim3 grid((Vv + 63) / 64, ((Tt - 1) * Bb) / 64);  // 157 x 20
        gemm_nt<64, 64, 32, 4, 4><<<grid, 256>>>(
            hall, W_lin, nullptr, b_lin, nullptr, out, (Tt - 1) * Bb, Vv, Kk);
    }
}

// round 2
// speedup vs baseline: 1.5734x; 1.5734x over previous
#include <cuda_runtime.h>
#include <math.h>

#define Bb 64
#define Tt 21
#define Ee 512
#define Hh 512
#define Vv 10000
#define G4 2048
#define Kk 512

#define REC_CTAS 128

// Scratch (static device memory; no cudaMalloc allowed)
__device__ float d_X[Tt * Bb * Ee];
__device__ float d_gpre[Tt * Bb * G4];
__device__ float d_hT[Hh * Bb];              // h transposed [512][64]
__device__ float d_hall[(Tt - 1) * Bb * Hh]; // row m = b*20 + s
__device__ unsigned g_cnt = 0;
__device__ unsigned g_flag = 0;

// ---------------------------------------------------------------- gather X
__global__ void build_x(const float* __restrict__ feat, const float* __restrict__ emb) {
    int idx = blockIdx.x * blockDim.x + threadIdx.x;
    if (idx >= Tt * Bb * Ee) return;
    int k = idx % Ee;
    int m = idx / Ee;
    int b = m % Bb;
    int t = m / Bb;
    d_X[idx] = (t == 0) ? feat[b * Ee + k] : emb[(b * Tt + (t - 1)) * Ee + k];
}

// ------------------------------------------------------ generic NT GEMM
// C[M,N] = A[M,K] * B[N,K]^T (+bias1) (+bias2). M % BM == 0, K % BK == 0.
template <int BM, int BN, int BK, int TM, int TN>
__global__ void gemm_nt(const float* __restrict__ A, const float* __restrict__ Bm,
                        const float* __restrict__ bias1, const float* __restrict__ bias2,
                        float* __restrict__ C, int M, int N, int K) {
    constexpr int THREADS = (BM / TM) * (BN / TN);
    __shared__ float As[BK][BM + 4];
    __shared__ float Bs[BK][BN + 4];

    const int tid = threadIdx.x;
    const int tx = tid % (BN / TN);
    const int ty = tid / (BN / TN);
    const int rowBase = blockIdx.y * BM;
    const int colBase = blockIdx.x * BN;

    float acc[TM][TN];
#pragma unroll
    for (int i = 0; i < TM; ++i)
#pragma unroll
        for (int j = 0; j < TN; ++j) acc[i][j] = 0.0f;

    for (int k0 = 0; k0 < K; k0 += BK) {
        for (int v = tid; v < BM * BK / 4; v += THREADS) {
            int r = v / (BK / 4);
            int c4 = v % (BK / 4);
            float4 val = *reinterpret_cast<const float4*>(
                &A[(size_t)(rowBase + r) * K + k0 + c4 * 4]);
            As[c4 * 4 + 0][r] = val.x;
            As[c4 * 4 + 1][r] = val.y;
            As[c4 * 4 + 2][r] = val.z;
            As[c4 * 4 + 3][r] = val.w;
        }
        for (int v = tid; v < BN * BK / 4; v += THREADS) {
            int r = v / (BK / 4);
            int c4 = v % (BK / 4);
            int n = colBase + r;
            float4 val = make_float4(0.f, 0.f, 0.f, 0.f);
            if (n < N)
                val = *reinterpret_cast<const float4*>(&Bm[(size_t)n * K + k0 + c4 * 4]);
            Bs[c4 * 4 + 0][r] = val.x;
            Bs[c4 * 4 + 1][r] = val.y;
            Bs[c4 * 4 + 2][r] = val.z;
            Bs[c4 * 4 + 3][r] = val.w;
        }
        __syncthreads();

#pragma unroll
        for (int k = 0; k < BK; ++k) {
            float a[TM], b[TN];
#pragma unroll
            for (int i = 0; i < TM; ++i) a[i] = As[k][ty * TM + i];
#pragma unroll
            for (int j = 0; j < TN; ++j) b[j] = Bs[k][tx * TN + j];
#pragma unroll
            for (int i = 0; i < TM; ++i)
#pragma unroll
                for (int j = 0; j < TN; ++j) acc[i][j] += a[i] * b[j];
        }
        __syncthreads();
    }

#pragma unroll
    for (int i = 0; i < TM; ++i) {
        int row = rowBase + ty * TM + i;
#pragma unroll
        for (int j = 0; j < TN; ++j) {
            int col = colBase + tx * TN + j;
            if (col < N) {
                float v = acc[i][j];
                if (bias1) v += bias1[col];
                if (bias2) v += bias2[col];
                C[(size_t)row * N + col] = v;
            }
        }
    }
}

// --------------------------------------------------- persistent recurrence
// 128 CTAs x 256 threads. CTA j owns h-cols 4j..4j+3 (16 gate rows of W_hh,
// cached in smem for all 20 steps). h transposed [512][64] in global.
// Split-k-4 matmul: 4 groups x 64 threads, TM=TN=4 register tiles.

__device__ __forceinline__ void grid_barrier() {
    __syncthreads();
    if (threadIdx.x == 0) {
        __threadfence();
        unsigned my = *((volatile unsigned*)&g_flag);
        unsigned old = atomicInc(&g_cnt, REC_CTAS - 1);  // wraps to 0 at REC_CTAS
        if (old == REC_CTAS - 1) {
            __threadfence();
            atomicAdd(&g_flag, 1);
        } else {
            while (*((volatile unsigned*)&g_flag) == my) {}
        }
    }
    __syncthreads();
}

__device__ __forceinline__ float sigf(float x) { return 1.0f / (1.0f + __expf(-x)); }

extern __shared__ float smem_rec[];
// layout: hTs [512][64] (32768) | Ws [512][16] (8192) | part [4][16][64] (4096)
#define SM_HTS 0
#define SM_WS  (512 * 64)
#define SM_PART (512 * 64 + 512 * 16)
#define REC_SMEM_BYTES ((512 * 64 + 512 * 16 + 4 * 16 * 64) * 4)

__global__ void __launch_bounds__(256, 1)
lstm_recurrence(const float* __restrict__ W_hh, const float* __restrict__ gpre,
                float* __restrict__ hT, float* __restrict__ hall) {
    float* hTs = smem_rec + SM_HTS;
    float* Ws = smem_rec + SM_WS;
    float* part = smem_rec + SM_PART;
    const int tid = threadIdx.x;
    const int cta = blockIdx.x;

    // Load W_hh slice transposed into smem: Ws[k][n], n = g*4 + c,
    // source row = g*512 + cta*4 + c. 16 rows x 512 = 8192 floats.
    for (int i = tid; i < 16 * 128; i += 256) {
        int n = i / 128;
        int k4 = i % 128;
        int g = n >> 2, c = n & 3;
        int row = g * 512 + cta * 4 + c;
        float4 v = *reinterpret_cast<const float4*>(&W_hh[(size_t)row * 512 + k4 * 4]);
        Ws[(k4 * 4 + 0) * 16 + n] = v.x;
        Ws[(k4 * 4 + 1) * 16 + n] = v.y;
        Ws[(k4 * 4 + 2) * 16 + n] = v.z;
        Ws[(k4 * 4 + 3) * 16 + n] = v.w;
    }

    // Elementwise identity: thread <-> (b, c)
    const int b = tid & 63;
    const int c = tid >> 6;  // 0..3
    const int hc = cta * 4 + c;

    // Matmul identity: group/threads
    const int grp = tid >> 6;         // 0..3 (k-split group)
    const int gtid = tid & 63;
    const int tm = gtid & 15;         // rows b = tm*4..tm*4+3
    const int tn = gtid >> 4;         // cols n = tn*4..tn*4+3

    float cs;  // cell state register for (b, hc)

    // ---- step 0: gates = gpre[0] (h=c=0)
    {
        const float* g0 = gpre + (size_t)b * G4;
        float i_ = sigf(g0[hc]);
        float f_ = sigf(g0[512 + hc]);  (void)f_;
        float gg = tanhf(g0[1024 + hc]);
        float o_ = sigf(g0[1536 + hc]);
        cs = i_ * gg;
        float hn = o_ * tanhf(cs);
        hT[hc * 64 + b] = hn;
    }
    grid_barrier();

    // ---- steps t = 1..20
    for (int t = 1; t < Tt; ++t) {
        // Stage h into smem (L2-coherent loads)
        {
            const float4* src = reinterpret_cast<const float4*>(hT);
            float4* dst = reinterpret_cast<float4*>(hTs);
            for (int i = tid; i < 512 * 64 / 4; i += 256) dst[i] = __ldcg(src + i);
        }
        __syncthreads();

        // Split-k matmul: this group's k range
        float acc[4][4];
#pragma unroll
        for (int i = 0; i < 4; ++i)
#pragma unroll
            for (int j = 0; j < 4; ++j) acc[i][j] = 0.0f;

        const int k0 = grp * 128;
#pragma unroll 4
        for (int k = k0; k < k0 + 128; ++k) {
            float4 a = *reinterpret_cast<float4*>(&hTs[k * 64 + tm * 4]);
            float4 w = *reinterpret_cast<float4*>(&Ws[k * 16 + tn * 4]);
            acc[0][0] += a.x * w.x; acc[0][1] += a.x * w.y; acc[0][2] += a.x * w.z; acc[0][3] += a.x * w.w;
            acc[1][0] += a.y * w.x; acc[1][1] += a.y * w.y; acc[1][2] += a.y * w.z; acc[1][3] += a.y * w.w;
            acc[2][0] += a.z * w.x; acc[2][1] += a.z * w.y; acc[2][2] += a.z * w.z; acc[2][3] += a.z * w.w;
            acc[3][0] += a.w * w.x; acc[3][1] += a.w * w.y; acc[3][2] += a.w * w.z; acc[3][3] += a.w * w.w;
        }

#pragma unroll
        for (int j = 0; j < 4; ++j)
#pragma unroll
            for (int i = 0; i < 4; ++i)
                part[grp * 1024 + (tn * 4 + j) * 64 + tm * 4 + i] = acc[i][j];
        __syncthreads();

        // Elementwise: reduce 4 partials per gate, add gpre, nonlinearity
        const float* gp = gpre + ((size_t)t * Bb + b) * G4;
        float gate[4];
#pragma unroll
        for (int g = 0; g < 4; ++g) {
            int n = g * 4 + c;
            float s = part[0 * 1024 + n * 64 + b] + part[1 * 1024 + n * 64 + b] +
                      part[2 * 1024 + n * 64 + b] + part[3 * 1024 + n * 64 + b];
            gate[g] = s + __ldg(&gp[g * 512 + hc]);
        }
        float i_ = sigf(gate[0]);
        float f_ = sigf(gate[1]);
        float g_ = tanhf(gate[2]);
        float o_ = sigf(gate[3]);
        cs = f_ * cs + i_ * g_;
        float hn = o_ * tanhf(cs);

        hall[((size_t)b * (Tt - 1) + (t - 1)) * Hh + hc] = hn;
        if (t < Tt - 1) {
            hT[hc * 64 + b] = hn;
            grid_barrier();
        }
    }
}

// ----------------------------------------------------------------- launch
extern "C" void kernel_launch(void* const* d_in, const int* in_sizes, int n_in,
                              void* d_out, int out_size) {
    const float* feat = (const float*)d_in[0];
    const float* emb = (const float*)d_in[1];
    const float* W_ih = (const float*)d_in[2];
    const float* W_hh = (const float*)d_in[3];
    const float* b_ih = (const float*)d_in[4];
    const float* b_hh = (const float*)d_in[5];
    const float* W_lin = (const float*)d_in[6];
    const float* b_lin = (const float*)d_in[7];
    float* out = (float*)d_out;

    float *X, *gpre, *hT, *hall;
    cudaGetSymbolAddress((void**)&X, d_X);
    cudaGetSymbolAddress((void**)&gpre, d_gpre);
    cudaGetSymbolAddress((void**)&hT, d_hT);
    cudaGetSymbolAddress((void**)&hall, d_hall);

    static int attr_set = 0;
    if (!attr_set) {
        cudaFuncSetAttribute(lstm_recurrence, cudaFuncAttributeMaxDynamicSharedMemorySize,
                             REC_SMEM_BYTES);
        attr_set = 1;
    }

    // 1) gather inputs
    build_x<<<(Tt * Bb * Ee + 255) / 256, 256>>>(feat, emb);

    // 2) precompute x@W_ih^T + (b_ih+b_hh) for all steps
    {
        dim3 grid(G4 / 64, (Tt * Bb) / 64);
        gemm_nt<64, 64, 32, 4, 4><<<grid, 256>>>(X, W_ih, b_ih, b_hh, gpre,
                                                 Tt * Bb, G4, Kk);
    }

    // 3) whole recurrence in one persistent kernel
    lstm_recurrence<<<REC_CTAS, 256, REC_SMEM_BYTES>>>(W_hh, gpre, hT, hall);

    // 4) projection: out[1280,10000] = hall @ W_lin^T + b_lin
    {
        dim3 grid((Vv + 63) / 64, ((Tt - 1) * Bb) / 128);
        gemm_nt<128, 64, 16, 8, 4><<<grid, 256>>>(hall, W_lin, b_lin, nullptr, out,
                                                  (Tt - 1) * Bb, Vv, Kk);
    }
}

// round 4
// speedup vs baseline: 2.3248x; 1.4776x over previous
#include <cuda_runtime.h>
#include <cuda_bf16.h>
#include <math.h>

#define Bb 64
#define Tt 21
#define Ee 512
#define Hh 512
#define Vv 10000
#define G4 2048
#define Kk 512

#define REC_CTAS 128

// ----------------------------------------------------------- scratch memory
__device__ __nv_bfloat16 d_Xhi[Tt * Bb * Ee];
__device__ __nv_bfloat16 d_Xlo[Tt * Bb * Ee];
__device__ __nv_bfloat16 d_Wihhi[G4 * Kk];
__device__ __nv_bfloat16 d_Wihlo[G4 * Kk];
__device__ __nv_bfloat16 d_Wlhi[Vv * Kk];
__device__ __nv_bfloat16 d_Wllo[Vv * Kk];
__device__ float d_gpre[Tt * Bb * G4];
__device__ float d_hT[Hh * Bb];
__device__ __nv_bfloat16 d_hallhi[(Tt - 1) * Bb * Hh];
__device__ __nv_bfloat16 d_halllo[(Tt - 1) * Bb * Hh];
__device__ unsigned g_cnt = 0;
__device__ unsigned g_flag = 0;

// ------------------------------------------------------------ split helpers
__device__ __forceinline__ void split2(float a, __nv_bfloat16& hi, __nv_bfloat16& lo) {
    hi = __float2bfloat16(a);
    lo = __float2bfloat16(a - __bfloat162float(hi));
}

__global__ void split_bf16(const float* __restrict__ in, __nv_bfloat16* __restrict__ hi,
                           __nv_bfloat16* __restrict__ lo, int n) {
    int idx = blockIdx.x * blockDim.x + threadIdx.x;
    if (idx >= n) return;
    split2(in[idx], hi[idx], lo[idx]);
}

// gather + split X (row m = t*64 + b)
__global__ void build_x(const float* __restrict__ feat, const float* __restrict__ emb) {
    int idx = blockIdx.x * blockDim.x + threadIdx.x;
    if (idx >= Tt * Bb * Ee) return;
    int k = idx % Ee;
    int m = idx / Ee;
    int b = m % Bb;
    int t = m / Bb;
    float v = (t == 0) ? feat[b * Ee + k] : emb[(b * Tt + (t - 1)) * Ee + k];
    split2(v, d_Xhi[idx], d_Xlo[idx]);
}

// ------------------------------------------------- bf16x3 tensor-core GEMM
// C[M,N] = A[M,K] * B[N,K]^T (+bias1) (+bias2), fp32 accum.
// A,B given as bf16 (hi, lo) pairs. 3 mma passes: hi*hi + lo*hi + hi*lo.
// BM=BN=128, BK=32, 256 threads, warp grid 4(m) x 2(n), warp tile 32x64.

__device__ __forceinline__ void mma_bf16(float* c, const unsigned* a, const unsigned* b) {
    asm volatile(
        "mma.sync.aligned.m16n8k16.row.col.f32.bf16.bf16.f32 "
        "{%0,%1,%2,%3}, {%4,%5,%6,%7}, {%8,%9}, {%0,%1,%2,%3};"
        : "+f"(c[0]), "+f"(c[1]), "+f"(c[2]), "+f"(c[3])
        : "r"(a[0]), "r"(a[1]), "r"(a[2]), "r"(a[3]), "r"(b[0]), "r"(b[1]));
}

__device__ __forceinline__ unsigned lds32(const __nv_bfloat16* p) {
    return *reinterpret_cast<const unsigned*>(p);
}

#define LDSP 40  // padded row stride in bf16 elements (80B = 20 banks, conflict-free frags)

__global__ void __launch_bounds__(256)
gemm_bf16x3(const __nv_bfloat16* __restrict__ Ahi, const __nv_bfloat16* __restrict__ Alo,
            const __nv_bfloat16* __restrict__ Bhi, const __nv_bfloat16* __restrict__ Blo,
            const float* __restrict__ bias1, const float* __restrict__ bias2,
            float* __restrict__ C, int M, int N, int K) {
    __shared__ __nv_bfloat16 sA[2][128 * LDSP];
    __shared__ __nv_bfloat16 sB[2][128 * LDSP];

    const int tid = threadIdx.x;
    const int warp = tid >> 5, lane = tid & 31;
    const int wm = warp >> 1, wn = warp & 1;
    const int g = lane >> 2, qp = lane & 3;
    const int row0 = blockIdx.y * 128, col0 = blockIdx.x * 128;

    float acc[2][8][4];
#pragma unroll
    for (int mi = 0; mi < 2; ++mi)
#pragma unroll
        for (int ni = 0; ni < 8; ++ni)
#pragma unroll
            for (int cc = 0; cc < 4; ++cc) acc[mi][ni][cc] = 0.0f;

    const uint4 zero4 = make_uint4(0, 0, 0, 0);

    for (int k0 = 0; k0 < K; k0 += 32) {
        // stage A hi/lo (128 rows x 32 bf16 = 4 uint4/row)
        for (int i = tid; i < 128 * 4; i += 256) {
            int r = i >> 2, c8 = i & 3;
            int gr = row0 + r;
            uint4 vh = zero4, vl = zero4;
            if (gr < M) {
                vh = *(reinterpret_cast<const uint4*>(Ahi + (size_t)gr * K + k0) + c8);
                vl = *(reinterpret_cast<const uint4*>(Alo + (size_t)gr * K + k0) + c8);
            }
            *reinterpret_cast<uint4*>(&sA[0][r * LDSP + c8 * 8]) = vh;
            *reinterpret_cast<uint4*>(&sA[1][r * LDSP + c8 * 8]) = vl;
        }
        // stage B hi/lo
        for (int i = tid; i < 128 * 4; i += 256) {
            int r = i >> 2, c8 = i & 3;
            int gc = col0 + r;
            uint4 vh = zero4, vl = zero4;
            if (gc < N) {
                vh = *(reinterpret_cast<const uint4*>(Bhi + (size_t)gc * K + k0) + c8);
                vl = *(reinterpret_cast<const uint4*>(Blo + (size_t)gc * K + k0) + c8);
            }
            *reinterpret_cast<uint4*>(&sB[0][r * LDSP + c8 * 8]) = vh;
            *reinterpret_cast<uint4*>(&sB[1][r * LDSP + c8 * 8]) = vl;
        }
        __syncthreads();

#pragma unroll
        for (int kh = 0; kh < 32; kh += 16) {
            unsigned ah[2][4], al[2][4], bb[8][2];
#pragma unroll
            for (int mi = 0; mi < 2; ++mi) {
                int rb = wm * 32 + mi * 16;
                ah[mi][0] = lds32(&sA[0][(rb + g) * LDSP + kh + 2 * qp]);
                ah[mi][1] = lds32(&sA[0][(rb + 8 + g) * LDSP + kh + 2 * qp]);
                ah[mi][2] = lds32(&sA[0][(rb + g) * LDSP + kh + 8 + 2 * qp]);
                ah[mi][3] = lds32(&sA[0][(rb + 8 + g) * LDSP + kh + 8 + 2 * qp]);
                al[mi][0] = lds32(&sA[1][(rb + g) * LDSP + kh + 2 * qp]);
                al[mi][1] = lds32(&sA[1][(rb + 8 + g) * LDSP + kh + 2 * qp]);
                al[mi][2] = lds32(&sA[1][(rb + g) * LDSP + kh + 8 + 2 * qp]);
                al[mi][3] = lds32(&sA[1][(rb + 8 + g) * LDSP + kh + 8 + 2 * qp]);
            }
#pragma unroll
            for (int ni = 0; ni < 8; ++ni) {
                int cb = wn * 64 + ni * 8;
                bb[ni][0] = lds32(&sB[0][(cb + g) * LDSP + kh + 2 * qp]);
                bb[ni][1] = lds32(&sB[0][(cb + g) * LDSP + kh + 8 + 2 * qp]);
            }
#pragma unroll
            for (int mi = 0; mi < 2; ++mi)
#pragma unroll
                for (int ni = 0; ni < 8; ++ni) {
                    mma_bf16(acc[mi][ni], ah[mi], bb[ni]);
                    mma_bf16(acc[mi][ni], al[mi], bb[ni]);
                }
#pragma unroll
            for (int ni = 0; ni < 8; ++ni) {
                int cb = wn * 64 + ni * 8;
                bb[ni][0] = lds32(&sB[1][(cb + g) * LDSP + kh + 2 * qp]);
                bb[ni][1] = lds32(&sB[1][(cb + g) * LDSP + kh + 8 + 2 * qp]);
            }
#pragma unroll
            for (int mi = 0; mi < 2; ++mi)
#pragma unroll
                for (int ni = 0; ni < 8; ++ni) mma_bf16(acc[mi][ni], ah[mi], bb[ni]);
        }
        __syncthreads();
    }

    // epilogue
#pragma unroll
    for (int mi = 0; mi < 2; ++mi) {
#pragma unroll
        for (int half = 0; half < 2; ++half) {
            int row = row0 + wm * 32 + mi * 16 + g + half * 8;
            if (row >= M) continue;
#pragma unroll
            for (int ni = 0; ni < 8; ++ni) {
                int col = col0 + wn * 64 + ni * 8 + 2 * qp;
                if (col < N) {
                    float v0 = acc[mi][ni][half * 2 + 0];
                    float v1 = acc[mi][ni][half * 2 + 1];
                    float b0 = 0.f, b1v = 0.f;
                    if (bias1) { b0 += __ldg(&bias1[col]); b1v += __ldg(&bias1[col + 1]); }
                    if (bias2) { b0 += __ldg(&bias2[col]); b1v += __ldg(&bias2[col + 1]); }
                    C[(size_t)row * N + col] = v0 + b0;
                    C[(size_t)row * N + col + 1] = v1 + b1v;
                }
            }
        }
    }
}

// --------------------------------------------------- persistent recurrence
__device__ __forceinline__ void grid_barrier() {
    __syncthreads();
    if (threadIdx.x == 0) {
        __threadfence();
        unsigned my = *((volatile unsigned*)&g_flag);
        unsigned old = atomicInc(&g_cnt, REC_CTAS - 1);
        if (old == REC_CTAS - 1) {
            __threadfence();
            atomicAdd(&g_flag, 1);
        } else {
            while (*((volatile unsigned*)&g_flag) == my) {}
        }
    }
    __syncthreads();
}

__device__ __forceinline__ float sigf(float x) { return 1.0f / (1.0f + __expf(-x)); }

extern __shared__ float smem_rec[];
#define SM_HTS 0
#define SM_WS (512 * 64)
#define SM_PART (512 * 64 + 512 * 16)
#define REC_SMEM_BYTES ((512 * 64 + 512 * 16 + 4 * 16 * 64) * 4)

__global__ void __launch_bounds__(256, 1)
lstm_recurrence(const float* __restrict__ W_hh, const float* __restrict__ gpre,
                float* __restrict__ hT, __nv_bfloat16* __restrict__ hallhi,
                __nv_bfloat16* __restrict__ halllo) {
    float* hTs = smem_rec + SM_HTS;
    float* Ws = smem_rec + SM_WS;
    float* part = smem_rec + SM_PART;
    const int tid = threadIdx.x;
    const int cta = blockIdx.x;

    for (int i = tid; i < 16 * 128; i += 256) {
        int n = i / 128;
        int k4 = i % 128;
        int g = n >> 2, c = n & 3;
        int row = g * 512 + cta * 4 + c;
        float4 v = *reinterpret_cast<const float4*>(&W_hh[(size_t)row * 512 + k4 * 4]);
        Ws[(k4 * 4 + 0) * 16 + n] = v.x;
        Ws[(k4 * 4 + 1) * 16 + n] = v.y;
        Ws[(k4 * 4 + 2) * 16 + n] = v.z;
        Ws[(k4 * 4 + 3) * 16 + n] = v.w;
    }

    const int b = tid & 63;
    const int c = tid >> 6;
    const int hc = cta * 4 + c;

    const int grp = tid >> 6;
    const int gtid = tid & 63;
    const int tm = gtid & 15;
    const int tn = gtid >> 4;

    float cs;

    {
        const float* g0 = gpre + (size_t)b * G4;
        float i_ = sigf(g0[hc]);
        float gg = tanhf(g0[1024 + hc]);
        float o_ = sigf(g0[1536 + hc]);
        cs = i_ * gg;
        float hn = o_ * tanhf(cs);
        hT[hc * 64 + b] = hn;
    }
    grid_barrier();

    for (int t = 1; t < Tt; ++t) {
        {
            const float4* src = reinterpret_cast<const float4*>(hT);
            float4* dst = reinterpret_cast<float4*>(hTs);
            for (int i = tid; i < 512 * 64 / 4; i += 256) dst[i] = __ldcg(src + i);
        }
        __syncthreads();

        float acc[4][4];
#pragma unroll
        for (int i = 0; i < 4; ++i)
#pragma unroll
            for (int j = 0; j < 4; ++j) acc[i][j] = 0.0f;

        const int k0 = grp * 128;
#pragma unroll 4
        for (int k = k0; k < k0 + 128; ++k) {
            float4 a = *reinterpret_cast<float4*>(&hTs[k * 64 + tm * 4]);
            float4 w = *reinterpret_cast<float4*>(&Ws[k * 16 + tn * 4]);
            acc[0][0] += a.x * w.x; acc[0][1] += a.x * w.y; acc[0][2] += a.x * w.z; acc[0][3] += a.x * w.w;
            acc[1][0] += a.y * w.x; acc[1][1] += a.y * w.y; acc[1][2] += a.y * w.z; acc[1][3] += a.y * w.w;
            acc[2][0] += a.z * w.x; acc[2][1] += a.z * w.y; acc[2][2] += a.z * w.z; acc[2][3] += a.z * w.w;
            acc[3][0] += a.w * w.x; acc[3][1] += a.w * w.y; acc[3][2] += a.w * w.z; acc[3][3] += a.w * w.w;
        }

#pragma unroll
        for (int j = 0; j < 4; ++j)
#pragma unroll
            for (int i = 0; i < 4; ++i)
                part[grp * 1024 + (tn * 4 + j) * 64 + tm * 4 + i] = acc[i][j];
        __syncthreads();

        const float* gp = gpre + ((size_t)t * Bb + b) * G4;
        float gate[4];
#pragma unroll
        for (int g = 0; g < 4; ++g) {
            int n = g * 4 + c;
            float s = part[0 * 1024 + n * 64 + b] + part[1 * 1024 + n * 64 + b] +
                      part[2 * 1024 + n * 64 + b] + part[3 * 1024 + n * 64 + b];
            gate[g] = s + __ldg(&gp[g * 512 + hc]);
        }
        float i_ = sigf(gate[0]);
        float f_ = sigf(gate[1]);
        float g_ = tanhf(gate[2]);
        float o_ = sigf(gate[3]);
        cs = f_ * cs + i_ * g_;
        float hn = o_ * tanhf(cs);

        size_t hidx = ((size_t)b * (Tt - 1) + (t - 1)) * Hh + hc;
        __nv_bfloat16 hhi, hlo;
        split2(hn, hhi, hlo);
        hallhi[hidx] = hhi;
        halllo[hidx] = hlo;

        if (t < Tt - 1) {
            hT[hc * 64 + b] = hn;
            grid_barrier();
        }
    }
}

// ----------------------------------------------------------------- launch
extern "C" void kernel_launch(void* const* d_in, const int* in_sizes, int n_in,
                              void* d_out, int out_size) {
    const float* feat = (const float*)d_in[0];
    const float* emb = (const float*)d_in[1];
    const float* W_ih = (const float*)d_in[2];
    const float* W_hh = (const float*)d_in[3];
    const float* b_ih = (const float*)d_in[4];
    const float* b_hh = (const float*)d_in[5];
    const float* W_lin = (const float*)d_in[6];
    const float* b_lin = (const float*)d_in[7];
    float* out = (float*)d_out;

    float *gpre, *hT;
    __nv_bfloat16 *Xhi, *Xlo, *Wihhi, *Wihlo, *Wlhi, *Wllo, *hallhi, *halllo;
    cudaGetSymbolAddress((void**)&gpre, d_gpre);
    cudaGetSymbolAddress((void**)&hT, d_hT);
    cudaGetSymbolAddress((void**)&Xhi, d_Xhi);
    cudaGetSymbolAddress((void**)&Xlo, d_Xlo);
    cudaGetSymbolAddress((void**)&Wihhi, d_Wihhi);
    cudaGetSymbolAddress((void**)&Wihlo, d_Wihlo);
    cudaGetSymbolAddress((void**)&Wlhi, d_Wlhi);
    cudaGetSymbolAddress((void**)&Wllo, d_Wllo);
    cudaGetSymbolAddress((void**)&hallhi, d_hallhi);
    cudaGetSymbolAddress((void**)&halllo, d_halllo);

    // Idempotent, no static guard (harness forbids call-count-dependent behavior)
    cudaFuncSetAttribute(lstm_recurrence, cudaFuncAttributeMaxDynamicSharedMemorySize,
                         REC_SMEM_BYTES);

    // 1) gather + split X; split weights
    build_x<<<(Tt * Bb * Ee + 255) / 256, 256>>>(feat, emb);
    split_bf16<<<(G4 * Kk + 255) / 256, 256>>>(W_ih, Wihhi, Wihlo, G4 * Kk);
    split_bf16<<<(Vv * Kk + 255) / 256, 256>>>(W_lin, Wlhi, Wllo, Vv * Kk);

    // 2) precompute gpre = X @ W_ih^T + b_ih + b_hh  (tensor cores, bf16x3)
    {
        dim3 grid(G4 / 128, (Tt * Bb + 127) / 128);  // 16 x 11
        gemm_bf16x3<<<grid, 256>>>(Xhi, Xlo, Wihhi, Wihlo, b_ih, b_hh, gpre,
                                   Tt * Bb, G4, Kk);
    }

    // 3) recurrence (persistent kernel)
    lstm_recurrence<<<REC_CTAS, 256, REC_SMEM_BYTES>>>(W_hh, gpre, hT, hallhi, halllo);

    // 4) projection: out[1280,10000] = hall @ W_lin^T + b_lin (tensor cores)
    {
        dim3 grid((Vv + 127) / 128, ((Tt - 1) * Bb) / 128);  // 79 x 10
        gemm_bf16x3<<<grid, 256>>>(hallhi, halllo, Wlhi, Wllo, b_lin, nullptr, out,
                                   (Tt - 1) * Bb, Vv, Kk);
    }
}

// round 5
// speedup vs baseline: 2.4680x; 1.0616x over previous
#include <cuda_runtime.h>
#include <cuda_bf16.h>
#include <math.h>

#define Bb 64
#define Tt 21
#define Ee 512
#define Hh 512
#define Vv 10000
#define G4 2048
#define Kk 512

#define REC_CTAS 128

// ----------------------------------------------------------- scratch memory
__device__ __nv_bfloat16 d_Xhi[Tt * Bb * Ee];
__device__ __nv_bfloat16 d_Xlo[Tt * Bb * Ee];
__device__ __nv_bfloat16 d_Wihhi[G4 * Kk];
__device__ __nv_bfloat16 d_Wihlo[G4 * Kk];
__device__ __nv_bfloat16 d_Wlhi[Vv * Kk];
__device__ __nv_bfloat16 d_Wllo[Vv * Kk];
__device__ float d_gpre[Tt * Bb * G4];
__device__ float d_hT[Hh * Bb];
__device__ __nv_bfloat16 d_hallhi[(Tt - 1) * Bb * Hh];
__device__ __nv_bfloat16 d_halllo[(Tt - 1) * Bb * Hh];
__device__ unsigned g_cnt = 0;
__device__ unsigned g_flag = 0;

// ------------------------------------------------------------ split helpers
__device__ __forceinline__ void split2(float a, __nv_bfloat16& hi, __nv_bfloat16& lo) {
    hi = __float2bfloat16(a);
    lo = __float2bfloat16(a - __bfloat162float(hi));
}

__global__ void split_bf16(const float* __restrict__ in, __nv_bfloat16* __restrict__ hi,
                           __nv_bfloat16* __restrict__ lo, int n) {
    int idx = blockIdx.x * blockDim.x + threadIdx.x;
    if (idx >= n) return;
    split2(in[idx], hi[idx], lo[idx]);
}

// gather + split X (row m = t*64 + b)
__global__ void build_x(const float* __restrict__ feat, const float* __restrict__ emb) {
    int idx = blockIdx.x * blockDim.x + threadIdx.x;
    if (idx >= Tt * Bb * Ee) return;
    int k = idx % Ee;
    int m = idx / Ee;
    int b = m % Bb;
    int t = m / Bb;
    float v = (t == 0) ? feat[b * Ee + k] : emb[(b * Tt + (t - 1)) * Ee + k];
    split2(v, d_Xhi[idx], d_Xlo[idx]);
}

// ------------------------------------------------- bf16x3 tensor-core GEMM
// C[M,N] = A[M,K] * B[N,K]^T (+bias1) (+bias2), fp32 accum.
// 3 mma passes: hi*hi + lo*hi + hi*lo. BM=BN=128, BK=32, 256 threads.
// cp.async 2-stage pipeline + ldmatrix fragment loads.

__device__ __forceinline__ void mma_bf16(float* c, const unsigned* a, const unsigned* b) {
    asm volatile(
        "mma.sync.aligned.m16n8k16.row.col.f32.bf16.bf16.f32 "
        "{%0,%1,%2,%3}, {%4,%5,%6,%7}, {%8,%9}, {%0,%1,%2,%3};"
        : "+f"(c[0]), "+f"(c[1]), "+f"(c[2]), "+f"(c[3])
        : "r"(a[0]), "r"(a[1]), "r"(a[2]), "r"(a[3]), "r"(b[0]), "r"(b[1]));
}

__device__ __forceinline__ void cpa16(const __nv_bfloat16* smem_dst, const void* gsrc,
                                      int pred) {
    unsigned d = (unsigned)__cvta_generic_to_shared(smem_dst);
    asm volatile("cp.async.ca.shared.global [%0], [%1], 16, %2;" ::"r"(d), "l"(gsrc),
                 "r"(pred ? 16 : 0));
}

__device__ __forceinline__ void ldm_x4(unsigned* r, const __nv_bfloat16* p) {
    unsigned a = (unsigned)__cvta_generic_to_shared(p);
    asm volatile("ldmatrix.sync.aligned.m8n8.x4.shared.b16 {%0,%1,%2,%3}, [%4];"
                 : "=r"(r[0]), "=r"(r[1]), "=r"(r[2]), "=r"(r[3])
                 : "r"(a));
}

__device__ __forceinline__ void ldm_x2(unsigned* r, const __nv_bfloat16* p) {
    unsigned a = (unsigned)__cvta_generic_to_shared(p);
    asm volatile("ldmatrix.sync.aligned.m8n8.x2.shared.b16 {%0,%1}, [%2];"
                 : "=r"(r[0]), "=r"(r[1])
                 : "r"(a));
}

#define LDSP 40  // padded row stride in bf16 (80B): ldmatrix 8-row phases conflict-free
#define GEMM_TILE (128 * LDSP)
// tiles: stage*4 + {Ahi=0, Alo=1, Bhi=2, Blo=3}
#define GEMM_SMEM_BYTES (8 * GEMM_TILE * 2)

extern __shared__ __nv_bfloat16 gsm[];

__global__ void __launch_bounds__(256)
gemm_bf16x3(const __nv_bfloat16* __restrict__ Ahi, const __nv_bfloat16* __restrict__ Alo,
            const __nv_bfloat16* __restrict__ Bhi, const __nv_bfloat16* __restrict__ Blo,
            const float* __restrict__ bias1, const float* __restrict__ bias2,
            float* __restrict__ C, int M, int N, int K) {
    const int tid = threadIdx.x;
    const int warp = tid >> 5, lane = tid & 31;
    const int wm = warp >> 1, wn = warp & 1;
    const int g = lane >> 2, qp = lane & 3;
    const int row0 = blockIdx.y * 128, col0 = blockIdx.x * 128;

    float acc[2][8][4];
#pragma unroll
    for (int mi = 0; mi < 2; ++mi)
#pragma unroll
        for (int ni = 0; ni < 8; ++ni)
#pragma unroll
            for (int cc = 0; cc < 4; ++cc) acc[mi][ni][cc] = 0.0f;

    // ldmatrix per-lane source addresses (within a tile, given rb/cb/kh at use site)
    const int a_sel = lane >> 3;            // 0..3
    const int a_row = (lane & 7) + (a_sel & 1) * 8;   // + rb
    const int a_col = (a_sel >> 1) * 8;               // + kh
    const int b_row = lane & 7;                       // + cb (lanes 16+ repeat, unused)
    const int b_col = ((lane >> 3) & 1) * 8;          // + kh

    const int ktiles = K / 32;

    // stage loader: 128 rows x 4 16B-chunks per tile, 4 tiles
    auto stage_load = [&](int kt, int s) {
        const int k0 = kt * 32;
        __nv_bfloat16* tAh = gsm + (s * 4 + 0) * GEMM_TILE;
        __nv_bfloat16* tAl = gsm + (s * 4 + 1) * GEMM_TILE;
        __nv_bfloat16* tBh = gsm + (s * 4 + 2) * GEMM_TILE;
        __nv_bfloat16* tBl = gsm + (s * 4 + 3) * GEMM_TILE;
        for (int i = tid; i < 512; i += 256) {
            int r = i >> 2, c = i & 3;
            int gr = row0 + r, gc = col0 + r;
            int pa = gr < M, pb = gc < N;
            size_t oA = (size_t)(pa ? gr : 0) * K + k0 + c * 8;
            size_t oB = (size_t)(pb ? gc : 0) * K + k0 + c * 8;
            int so = r * LDSP + c * 8;
            cpa16(tAh + so, Ahi + oA, pa);
            cpa16(tAl + so, Alo + oA, pa);
            cpa16(tBh + so, Bhi + oB, pb);
            cpa16(tBl + so, Blo + oB, pb);
        }
    };

    stage_load(0, 0);
    asm volatile("cp.async.commit_group;");

    for (int kt = 0; kt < ktiles; ++kt) {
        const int s = kt & 1;
        if (kt + 1 < ktiles) {
            stage_load(kt + 1, s ^ 1);
            asm volatile("cp.async.commit_group;");
            asm volatile("cp.async.wait_group 1;");
        } else {
            asm volatile("cp.async.wait_group 0;");
        }
        __syncthreads();

        const __nv_bfloat16* tAh = gsm + (s * 4 + 0) * GEMM_TILE;
        const __nv_bfloat16* tAl = gsm + (s * 4 + 1) * GEMM_TILE;
        const __nv_bfloat16* tBh = gsm + (s * 4 + 2) * GEMM_TILE;
        const __nv_bfloat16* tBl = gsm + (s * 4 + 3) * GEMM_TILE;

#pragma unroll
        for (int kh = 0; kh < 32; kh += 16) {
            unsigned ah[2][4], al[2][4], bb[8][2];
#pragma unroll
            for (int mi = 0; mi < 2; ++mi) {
                int rb = wm * 32 + mi * 16;
                ldm_x4(ah[mi], &tAh[(rb + a_row) * LDSP + kh + a_col]);
                ldm_x4(al[mi], &tAl[(rb + a_row) * LDSP + kh + a_col]);
            }
#pragma unroll
            for (int ni = 0; ni < 8; ++ni) {
                int cb = wn * 64 + ni * 8;
                ldm_x2(bb[ni], &tBh[(cb + b_row) * LDSP + kh + b_col]);
            }
#pragma unroll
            for (int mi = 0; mi < 2; ++mi)
#pragma unroll
                for (int ni = 0; ni < 8; ++ni) {
                    mma_bf16(acc[mi][ni], ah[mi], bb[ni]);
                    mma_bf16(acc[mi][ni], al[mi], bb[ni]);
                }
#pragma unroll
            for (int ni = 0; ni < 8; ++ni) {
                int cb = wn * 64 + ni * 8;
                ldm_x2(bb[ni], &tBl[(cb + b_row) * LDSP + kh + b_col]);
            }
#pragma unroll
            for (int mi = 0; mi < 2; ++mi)
#pragma unroll
                for (int ni = 0; ni < 8; ++ni) mma_bf16(acc[mi][ni], ah[mi], bb[ni]);
        }
        __syncthreads();
    }

    // epilogue
#pragma unroll
    for (int mi = 0; mi < 2; ++mi) {
#pragma unroll
        for (int half = 0; half < 2; ++half) {
            int row = row0 + wm * 32 + mi * 16 + g + half * 8;
            if (row >= M) continue;
#pragma unroll
            for (int ni = 0; ni < 8; ++ni) {
                int col = col0 + wn * 64 + ni * 8 + 2 * qp;
                if (col < N) {
                    float v0 = acc[mi][ni][half * 2 + 0];
                    float v1 = acc[mi][ni][half * 2 + 1];
                    float b0 = 0.f, b1v = 0.f;
                    if (bias1) { b0 += __ldg(&bias1[col]); b1v += __ldg(&bias1[col + 1]); }
                    if (bias2) { b0 += __ldg(&bias2[col]); b1v += __ldg(&bias2[col + 1]); }
                    C[(size_t)row * N + col] = v0 + b0;
                    C[(size_t)row * N + col + 1] = v1 + b1v;
                }
            }
        }
    }
}

// --------------------------------------------------- persistent recurrence
__device__ __forceinline__ void grid_barrier() {
    __syncthreads();
    if (threadIdx.x == 0) {
        __threadfence();
        unsigned my = *((volatile unsigned*)&g_flag);
        unsigned old = atomicInc(&g_cnt, REC_CTAS - 1);
        if (old == REC_CTAS - 1) {
            __threadfence();
            atomicAdd(&g_flag, 1);
        } else {
            while (*((volatile unsigned*)&g_flag) == my) {}
        }
    }
    __syncthreads();
}

__device__ __forceinline__ float sigf(float x) { return 1.0f / (1.0f + __expf(-x)); }

extern __shared__ float smem_rec[];
#define SM_HTS 0
#define SM_WS (512 * 64)
#define SM_PART (512 * 64 + 512 * 16)
#define REC_SMEM_BYTES ((512 * 64 + 512 * 16 + 4 * 16 * 64) * 4)

__global__ void __launch_bounds__(256, 1)
lstm_recurrence(const float* __restrict__ W_hh, const float* __restrict__ gpre,
                float* __restrict__ hT, __nv_bfloat16* __restrict__ hallhi,
                __nv_bfloat16* __restrict__ halllo) {
    float* hTs = smem_rec + SM_HTS;
    float* Ws = smem_rec + SM_WS;
    float* part = smem_rec + SM_PART;
    const int tid = threadIdx.x;
    const int cta = blockIdx.x;

    for (int i = tid; i < 16 * 128; i += 256) {
        int n = i / 128;
        int k4 = i % 128;
        int g = n >> 2, c = n & 3;
        int row = g * 512 + cta * 4 + c;
        float4 v = *reinterpret_cast<const float4*>(&W_hh[(size_t)row * 512 + k4 * 4]);
        Ws[(k4 * 4 + 0) * 16 + n] = v.x;
        Ws[(k4 * 4 + 1) * 16 + n] = v.y;
        Ws[(k4 * 4 + 2) * 16 + n] = v.z;
        Ws[(k4 * 4 + 3) * 16 + n] = v.w;
    }

    const int b = tid & 63;
    const int c = tid >> 6;
    const int hc = cta * 4 + c;

    const int grp = tid >> 6;
    const int gtid = tid & 63;
    const int tm = gtid & 15;
    const int tn = gtid >> 4;

    float cs;

    {
        const float* g0 = gpre + (size_t)b * G4;
        float i_ = sigf(g0[hc]);
        float gg = tanhf(g0[1024 + hc]);
        float o_ = sigf(g0[1536 + hc]);
        cs = i_ * gg;
        float hn = o_ * tanhf(cs);
        hT[hc * 64 + b] = hn;
    }
    grid_barrier();

    for (int t = 1; t < Tt; ++t) {
        {
            const float4* src = reinterpret_cast<const float4*>(hT);
            float4* dst = reinterpret_cast<float4*>(hTs);
            for (int i = tid; i < 512 * 64 / 4; i += 256) dst[i] = __ldcg(src + i);
        }
        __syncthreads();

        float acc[4][4];
#pragma unroll
        for (int i = 0; i < 4; ++i)
#pragma unroll
            for (int j = 0; j < 4; ++j) acc[i][j] = 0.0f;

        const int k0 = grp * 128;
#pragma unroll 4
        for (int k = k0; k < k0 + 128; ++k) {
            float4 a = *reinterpret_cast<float4*>(&hTs[k * 64 + tm * 4]);
            float4 w = *reinterpret_cast<float4*>(&Ws[k * 16 + tn * 4]);
            acc[0][0] += a.x * w.x; acc[0][1] += a.x * w.y; acc[0][2] += a.x * w.z; acc[0][3] += a.x * w.w;
            acc[1][0] += a.y * w.x; acc[1][1] += a.y * w.y; acc[1][2] += a.y * w.z; acc[1][3] += a.y * w.w;
            acc[2][0] += a.z * w.x; acc[2][1] += a.z * w.y; acc[2][2] += a.z * w.z; acc[2][3] += a.z * w.w;
            acc[3][0] += a.w * w.x; acc[3][1] += a.w * w.y; acc[3][2] += a.w * w.z; acc[3][3] += a.w * w.w;
        }

#pragma unroll
        for (int j = 0; j < 4; ++j)
#pragma unroll
            for (int i = 0; i < 4; ++i)
                part[grp * 1024 + (tn * 4 + j) * 64 + tm * 4 + i] = acc[i][j];
        __syncthreads();

        const float* gp = gpre + ((size_t)t * Bb + b) * G4;
        float gate[4];
#pragma unroll
        for (int g = 0; g < 4; ++g) {
            int n = g * 4 + c;
            float s = part[0 * 1024 + n * 64 + b] + part[1 * 1024 + n * 64 + b] +
                      part[2 * 1024 + n * 64 + b] + part[3 * 1024 + n * 64 + b];
            gate[g] = s + __ldg(&gp[g * 512 + hc]);
        }
        float i_ = sigf(gate[0]);
        float f_ = sigf(gate[1]);
        float g_ = tanhf(gate[2]);
        float o_ = sigf(gate[3]);
        cs = f_ * cs + i_ * g_;
        float hn = o_ * tanhf(cs);

        size_t hidx = ((size_t)b * (Tt - 1) + (t - 1)) * Hh + hc;
        __nv_bfloat16 hhi, hlo;
        split2(hn, hhi, hlo);
        hallhi[hidx] = hhi;
        halllo[hidx] = hlo;

        if (t < Tt - 1) {
            hT[hc * 64 + b] = hn;
            grid_barrier();
        }
    }
}

// ----------------------------------------------------------------- launch
extern "C" void kernel_launch(void* const* d_in, const int* in_sizes, int n_in,
                              void* d_out, int out_size) {
    const float* feat = (const float*)d_in[0];
    const float* emb = (const float*)d_in[1];
    const float* W_ih = (const float*)d_in[2];
    const float* W_hh = (const float*)d_in[3];
    const float* b_ih = (const float*)d_in[4];
    const float* b_hh = (const float*)d_in[5];
    const float* W_lin = (const float*)d_in[6];
    const float* b_lin = (const float*)d_in[7];
    float* out = (float*)d_out;

    float *gpre, *hT;
    __nv_bfloat16 *Xhi, *Xlo, *Wihhi, *Wihlo, *Wlhi, *Wllo, *hallhi, *halllo;
    cudaGetSymbolAddress((void**)&gpre, d_gpre);
    cudaGetSymbolAddress((void**)&hT, d_hT);
    cudaGetSymbolAddress((void**)&Xhi, d_Xhi);
    cudaGetSymbolAddress((void**)&Xlo, d_Xlo);
    cudaGetSymbolAddress((void**)&Wihhi, d_Wihhi);
    cudaGetSymbolAddress((void**)&Wihlo, d_Wihlo);
    cudaGetSymbolAddress((void**)&Wlhi, d_Wlhi);
    cudaGetSymbolAddress((void**)&Wllo, d_Wllo);
    cudaGetSymbolAddress((void**)&hallhi, d_hallhi);
    cudaGetSymbolAddress((void**)&halllo, d_halllo);

    // Idempotent (no static guards allowed)
    cudaFuncSetAttribute(lstm_recurrence, cudaFuncAttributeMaxDynamicSharedMemorySize,
                         REC_SMEM_BYTES);
    cudaFuncSetAttribute(gemm_bf16x3, cudaFuncAttributeMaxDynamicSharedMemorySize,
                         GEMM_SMEM_BYTES);

    // 1) gather + split X; split weights
    build_x<<<(Tt * Bb * Ee + 255) / 256, 256>>>(feat, emb);
    split_bf16<<<(G4 * Kk + 255) / 256, 256>>>(W_ih, Wihhi, Wihlo, G4 * Kk);
    split_bf16<<<(Vv * Kk + 255) / 256, 256>>>(W_lin, Wlhi, Wllo, Vv * Kk);

    // 2) precompute gpre = X @ W_ih^T + b_ih + b_hh
    {
        dim3 grid(G4 / 128, (Tt * Bb + 127) / 128);  // 16 x 11
        gemm_bf16x3<<<grid, 256, GEMM_SMEM_BYTES>>>(Xhi, Xlo, Wihhi, Wihlo, b_ih, b_hh,
                                                    gpre, Tt * Bb, G4, Kk);
    }

    // 3) recurrence (persistent kernel)
    lstm_recurrence<<<REC_CTAS, 256, REC_SMEM_BYTES>>>(W_hh, gpre, hT, hallhi, halllo);

    // 4) projection: out[1280,10000] = hall @ W_lin^T + b_lin
    {
        dim3 grid((Vv + 127) / 128, ((Tt - 1) * Bb) / 128);  // 79 x 10
        gemm_bf16x3<<<grid, 256, GEMM_SMEM_BYTES>>>(hallhi, halllo, Wlhi, Wllo, b_lin,
                                                    nullptr, out, (Tt - 1) * Bb, Vv, Kk);
    }
}

// round 7
// speedup vs baseline: 2.7388x; 1.1097x over previous
#include <cuda_runtime.h>
#include <cuda_bf16.h>
#include <math.h>

#define Bb 64
#define Tt 21
#define Ee 512
#define Hh 512
#define Vv 10000
#define G4 2048
#define Kk 512

#define REC_CTAS 128

// ----------------------------------------------------------- scratch memory
__device__ __nv_bfloat16 d_Xhi[Tt * Bb * Ee];
__device__ __nv_bfloat16 d_Xlo[Tt * Bb * Ee];
__device__ __nv_bfloat16 d_Wihhi[G4 * Kk];
__device__ __nv_bfloat16 d_Wihlo[G4 * Kk];
__device__ __nv_bfloat16 d_Wlhi[Vv * Kk];
__device__ __nv_bfloat16 d_Wllo[Vv * Kk];
__device__ float d_gpre[Tt * Bb * G4];
__device__ __nv_bfloat16 d_hhi[Bb * Hh];   // h hi, row-major [b][hc]
__device__ __nv_bfloat16 d_hlo[Bb * Hh];   // h lo
__device__ __nv_bfloat16 d_hallhi[(Tt - 1) * Bb * Hh];
__device__ __nv_bfloat16 d_halllo[(Tt - 1) * Bb * Hh];
__device__ unsigned g_cnt = 0;
__device__ unsigned g_flag = 0;

// ------------------------------------------------------------ split helpers
__device__ __forceinline__ void split2(float a, __nv_bfloat16& hi, __nv_bfloat16& lo) {
    hi = __float2bfloat16(a);
    lo = __float2bfloat16(a - __bfloat162float(hi));
}

__global__ void split_bf16(const float* __restrict__ in, __nv_bfloat16* __restrict__ hi,
                           __nv_bfloat16* __restrict__ lo, int n) {
    int idx = blockIdx.x * blockDim.x + threadIdx.x;
    if (idx >= n) return;
    split2(in[idx], hi[idx], lo[idx]);
}

// gather + split X (row m = t*64 + b)
__global__ void build_x(const float* __restrict__ feat, const float* __restrict__ emb) {
    int idx = blockIdx.x * blockDim.x + threadIdx.x;
    if (idx >= Tt * Bb * Ee) return;
    int k = idx % Ee;
    int m = idx / Ee;
    int b = m % Bb;
    int t = m / Bb;
    float v = (t == 0) ? feat[b * Ee + k] : emb[(b * Tt + (t - 1)) * Ee + k];
    split2(v, d_Xhi[idx], d_Xlo[idx]);
}

// --------------------------------------------------------------- mma helpers
__device__ __forceinline__ void mma_bf16(float* c, const unsigned* a, const unsigned* b) {
    asm volatile(
        "mma.sync.aligned.m16n8k16.row.col.f32.bf16.bf16.f32 "
        "{%0,%1,%2,%3}, {%4,%5,%6,%7}, {%8,%9}, {%0,%1,%2,%3};"
        : "+f"(c[0]), "+f"(c[1]), "+f"(c[2]), "+f"(c[3])
        : "r"(a[0]), "r"(a[1]), "r"(a[2]), "r"(a[3]), "r"(b[0]), "r"(b[1]));
}

// cp.async.ca — L1+L2 (safe for inputs produced by a prior kernel launch)
__device__ __forceinline__ void cpa16(const __nv_bfloat16* smem_dst, const void* gsrc,
                                      int pred) {
    unsigned d = (unsigned)__cvta_generic_to_shared(smem_dst);
    asm volatile("cp.async.ca.shared.global [%0], [%1], 16, %2;" ::"r"(d), "l"(gsrc),
                 "r"(pred ? 16 : 0));
}

// cp.async.cg — L2 only (coherent across SMs within a persistent kernel)
__device__ __forceinline__ void cpa16_cg(const __nv_bfloat16* smem_dst, const void* gsrc) {
    unsigned d = (unsigned)__cvta_generic_to_shared(smem_dst);
    asm volatile("cp.async.cg.shared.global [%0], [%1], 16;" ::"r"(d), "l"(gsrc));
}

__device__ __forceinline__ void ldm_x4(unsigned* r, const __nv_bfloat16* p) {
    unsigned a = (unsigned)__cvta_generic_to_shared(p);
    asm volatile("ldmatrix.sync.aligned.m8n8.x4.shared.b16 {%0,%1,%2,%3}, [%4];"
                 : "=r"(r[0]), "=r"(r[1]), "=r"(r[2]), "=r"(r[3])
                 : "r"(a));
}

__device__ __forceinline__ void ldm_x2(unsigned* r, const __nv_bfloat16* p) {
    unsigned a = (unsigned)__cvta_generic_to_shared(p);
    asm volatile("ldmatrix.sync.aligned.m8n8.x2.shared.b16 {%0,%1}, [%2];"
                 : "=r"(r[0]), "=r"(r[1])
                 : "r"(a));
}

// ------------------------------------------------- bf16x3 tensor-core GEMM
// C[M,N] = A[M,K] * B[N,K]^T (+bias1) (+bias2), fp32 accum. 3 mma passes.
// BM=BN=128, BK=32, 256 threads, cp.async 2-stage pipeline, ldmatrix loads.

#define LDSP 40
#define GEMM_TILE (128 * LDSP)
#define GEMM_SMEM_BYTES (8 * GEMM_TILE * 2)

extern __shared__ __nv_bfloat16 gsm[];

__global__ void __launch_bounds__(256)
gemm_bf16x3(const __nv_bfloat16* __restrict__ Ahi, const __nv_bfloat16* __restrict__ Alo,
            const __nv_bfloat16* __restrict__ Bhi, const __nv_bfloat16* __restrict__ Blo,
            const float* __restrict__ bias1, const float* __restrict__ bias2,
            float* __restrict__ C, int M, int N, int K) {
    const int tid = threadIdx.x;
    const int warp = tid >> 5, lane = tid & 31;
    const int wm = warp >> 1, wn = warp & 1;
    const int g = lane >> 2, qp = lane & 3;
    const int row0 = blockIdx.y * 128, col0 = blockIdx.x * 128;

    float acc[2][8][4];
#pragma unroll
    for (int mi = 0; mi < 2; ++mi)
#pragma unroll
        for (int ni = 0; ni < 8; ++ni)
#pragma unroll
            for (int cc = 0; cc < 4; ++cc) acc[mi][ni][cc] = 0.0f;

    const int a_sel = lane >> 3;
    const int a_row = (lane & 7) + (a_sel & 1) * 8;
    const int a_col = (a_sel >> 1) * 8;
    const int b_row = lane & 7;
    const int b_col = ((lane >> 3) & 1) * 8;

    const int ktiles = K / 32;

    auto stage_load = [&](int kt, int s) {
        const int k0 = kt * 32;
        __nv_bfloat16* tAh = gsm + (s * 4 + 0) * GEMM_TILE;
        __nv_bfloat16* tAl = gsm + (s * 4 + 1) * GEMM_TILE;
        __nv_bfloat16* tBh = gsm + (s * 4 + 2) * GEMM_TILE;
        __nv_bfloat16* tBl = gsm + (s * 4 + 3) * GEMM_TILE;
        for (int i = tid; i < 512; i += 256) {
            int r = i >> 2, c = i & 3;
            int gr = row0 + r, gc = col0 + r;
            int pa = gr < M, pb = gc < N;
            size_t oA = (size_t)(pa ? gr : 0) * K + k0 + c * 8;
            size_t oB = (size_t)(pb ? gc : 0) * K + k0 + c * 8;
            int so = r * LDSP + c * 8;
            cpa16(tAh + so, Ahi + oA, pa);
            cpa16(tAl + so, Alo + oA, pa);
            cpa16(tBh + so, Bhi + oB, pb);
            cpa16(tBl + so, Blo + oB, pb);
        }
    };

    stage_load(0, 0);
    asm volatile("cp.async.commit_group;");

    for (int kt = 0; kt < ktiles; ++kt) {
        const int s = kt & 1;
        if (kt + 1 < ktiles) {
            stage_load(kt + 1, s ^ 1);
            asm volatile("cp.async.commit_group;");
            asm volatile("cp.async.wait_group 1;");
        } else {
            asm volatile("cp.async.wait_group 0;");
        }
        __syncthreads();

        const __nv_bfloat16* tAh = gsm + (s * 4 + 0) * GEMM_TILE;
        const __nv_bfloat16* tAl = gsm + (s * 4 + 1) * GEMM_TILE;
        const __nv_bfloat16* tBh = gsm + (s * 4 + 2) * GEMM_TILE;
        const __nv_bfloat16* tBl = gsm + (s * 4 + 3) * GEMM_TILE;

#pragma unroll
        for (int kh = 0; kh < 32; kh += 16) {
            unsigned ah[2][4], al[2][4], bb[8][2];
#pragma unroll
            for (int mi = 0; mi < 2; ++mi) {
                int rb = wm * 32 + mi * 16;
                ldm_x4(ah[mi], &tAh[(rb + a_row) * LDSP + kh + a_col]);
                ldm_x4(al[mi], &tAl[(rb + a_row) * LDSP + kh + a_col]);
            }
#pragma unroll
            for (int ni = 0; ni < 8; ++ni) {
                int cb = wn * 64 + ni * 8;
                ldm_x2(bb[ni], &tBh[(cb + b_row) * LDSP + kh + b_col]);
            }
#pragma unroll
            for (int mi = 0; mi < 2; ++mi)
#pragma unroll
                for (int ni = 0; ni < 8; ++ni) {
                    mma_bf16(acc[mi][ni], ah[mi], bb[ni]);
                    mma_bf16(acc[mi][ni], al[mi], bb[ni]);
                }
#pragma unroll
            for (int ni = 0; ni < 8; ++ni) {
                int cb = wn * 64 + ni * 8;
                ldm_x2(bb[ni], &tBl[(cb + b_row) * LDSP + kh + b_col]);
            }
#pragma unroll
            for (int mi = 0; mi < 2; ++mi)
#pragma unroll
                for (int ni = 0; ni < 8; ++ni) mma_bf16(acc[mi][ni], ah[mi], bb[ni]);
        }
        __syncthreads();
    }

#pragma unroll
    for (int mi = 0; mi < 2; ++mi) {
#pragma unroll
        for (int half = 0; half < 2; ++half) {
            int row = row0 + wm * 32 + mi * 16 + g + half * 8;
            if (row >= M) continue;
#pragma unroll
            for (int ni = 0; ni < 8; ++ni) {
                int col = col0 + wn * 64 + ni * 8 + 2 * qp;
                if (col < N) {
                    float v0 = acc[mi][ni][half * 2 + 0];
                    float v1 = acc[mi][ni][half * 2 + 1];
                    float b0 = 0.f, b1v = 0.f;
                    if (bias1) { b0 += __ldg(&bias1[col]); b1v += __ldg(&bias1[col + 1]); }
                    if (bias2) { b0 += __ldg(&bias2[col]); b1v += __ldg(&bias2[col + 1]); }
                    C[(size_t)row * N + col] = v0 + b0;
                    C[(size_t)row * N + col + 1] = v1 + b1v;
                }
            }
        }
    }
}

// --------------------------------------------------- persistent recurrence
// 128 CTAs x 256 threads. CTA j owns h-cols 4j..4j+3 = 16 gate rows of W_hh.
// Step matmul on tensor cores (bf16x3): M=64 batch, N=16 gates, K=512.
// 8 warps = 4 m-tiles x 2 k-halves; partials reduced via smem.

__device__ __forceinline__ void grid_barrier() {
    __syncthreads();
    if (threadIdx.x == 0) {
        __threadfence();
        unsigned my = *((volatile unsigned*)&g_flag);
        unsigned old = atomicInc(&g_cnt, REC_CTAS - 1);
        if (old == REC_CTAS - 1) {
            __threadfence();
            atomicAdd(&g_flag, 1);
        } else {
            while (*((volatile unsigned*)&g_flag) == my) {}
        }
    }
    __syncthreads();
}

__device__ __forceinline__ float sigf(float x) { return 1.0f / (1.0f + __expf(-x)); }

#define RLDS 520  // row stride in bf16: r*1040B mod 128B distinct per 8-row group
// smem (bf16 units): hHi[64*RLDS] | hLo[64*RLDS] | wHi[16*RLDS] | wLo[16*RLDS] | part(float)
#define REC_SMEM_BYTES (160 * RLDS * 2 + 2 * 64 * 16 * 4)

extern __shared__ __nv_bfloat16 rsm[];

__global__ void __launch_bounds__(256, 1)
lstm_recurrence(const float* __restrict__ W_hh, const float* __restrict__ gpre,
                __nv_bfloat16* __restrict__ hhiG, __nv_bfloat16* __restrict__ hloG,
                __nv_bfloat16* __restrict__ hallhi, __nv_bfloat16* __restrict__ halllo) {
    __nv_bfloat16* hHi = rsm;
    __nv_bfloat16* hLo = rsm + 64 * RLDS;
    __nv_bfloat16* wHi = rsm + 128 * RLDS;
    __nv_bfloat16* wLo = rsm + 144 * RLDS;
    float* part = (float*)(rsm + 160 * RLDS);  // [2][64][16]

    const int tid = threadIdx.x;
    const int cta = blockIdx.x;
    const int warp = tid >> 5, lane = tid & 31;

    // W slice rows n = g*4 + c  ->  W_hh[g*512 + cta*4 + c], split to bf16 hi/lo
    for (int i = tid; i < 16 * 512; i += 256) {
        int n = i >> 9;
        int k = i & 511;
        int g = n >> 2, c = n & 3;
        float w = __ldg(&W_hh[(size_t)(g * 512 + cta * 4 + c) * 512 + k]);
        __nv_bfloat16 hi, lo;
        split2(w, hi, lo);
        wHi[n * RLDS + k] = hi;
        wLo[n * RLDS + k] = lo;
    }

    const int b = tid & 63;
    const int c = tid >> 6;
    const int hc = cta * 4 + c;

    // mma identities
    const int mt = warp & 3;   // m-tile: batch rows mt*16..mt*16+15
    const int kh = warp >> 2;  // k-half: 0 -> k 0..255, 1 -> 256..511
    const int gq = lane >> 2, qp = lane & 3;
    const int a_sel = lane >> 3;
    const int a_row = (lane & 7) + (a_sel & 1) * 8;
    const int a_col = (a_sel >> 1) * 8;
    const int b_row = lane & 7;
    const int b_col = ((lane >> 3) & 1) * 8;

    float cs;

    // ---- step 0: h,c = 0 -> gates = gpre[0]
    {
        const float* g0 = gpre + (size_t)b * G4;
        float i_ = sigf(g0[hc]);
        float gg = tanhf(g0[1024 + hc]);
        float o_ = sigf(g0[1536 + hc]);
        cs = i_ * gg;
        float hn = o_ * tanhf(cs);
        __nv_bfloat16 hh, hl;
        split2(hn, hh, hl);
        hhiG[b * Hh + hc] = hh;
        hloG[b * Hh + hc] = hl;
    }
    grid_barrier();

    for (int t = 1; t < Tt; ++t) {
        // stage h hi/lo [64][512] bf16 via cp.async.cg (L2-coherent).
        // FULL coverage: 64 rows x 64 16B-chunks (512 bf16 per row).
        for (int i = tid; i < 64 * 64; i += 256) {
            int r = i >> 6, ck = (i & 63) * 8;
            cpa16_cg(&hHi[r * RLDS + ck], hhiG + r * Hh + ck);
            cpa16_cg(&hLo[r * RLDS + ck], hloG + r * Hh + ck);
        }
        asm volatile("cp.async.commit_group;");
        asm volatile("cp.async.wait_group 0;");
        __syncthreads();

        float acc[2][4];
#pragma unroll
        for (int nt = 0; nt < 2; ++nt)
#pragma unroll
            for (int cc = 0; cc < 4; ++cc) acc[nt][cc] = 0.0f;

        const int k0 = kh * 256;
#pragma unroll 4
        for (int kt = 0; kt < 16; ++kt) {
            int kk = k0 + kt * 16;
            unsigned ah[4], al[4], bh0[2], bh1[2], bl0[2], bl1[2];
            ldm_x4(ah, &hHi[(mt * 16 + a_row) * RLDS + kk + a_col]);
            ldm_x4(al, &hLo[(mt * 16 + a_row) * RLDS + kk + a_col]);
            ldm_x2(bh0, &wHi[(0 + b_row) * RLDS + kk + b_col]);
            ldm_x2(bh1, &wHi[(8 + b_row) * RLDS + kk + b_col]);
            ldm_x2(bl0, &wLo[(0 + b_row) * RLDS + kk + b_col]);
            ldm_x2(bl1, &wLo[(8 + b_row) * RLDS + kk + b_col]);
            mma_bf16(acc[0], ah, bh0);
            mma_bf16(acc[1], ah, bh1);
            mma_bf16(acc[0], al, bh0);
            mma_bf16(acc[1], al, bh1);
            mma_bf16(acc[0], ah, bl0);
            mma_bf16(acc[1], ah, bl1);
        }

        // write partials: rows = batch, cols = gate-row n (0..15)
#pragma unroll
        for (int nt = 0; nt < 2; ++nt)
#pragma unroll
            for (int cc = 0; cc < 4; ++cc) {
                int row = mt * 16 + gq + (cc >> 1) * 8;
                int col = nt * 8 + 2 * qp + (cc & 1);
                part[kh * 1024 + row * 16 + col] = acc[nt][cc];
            }
        __syncthreads();

        // elementwise: combine k-halves, add gpre, nonlinearity
        const float* gp = gpre + ((size_t)t * Bb + b) * G4;
        float gate[4];
#pragma unroll
        for (int g = 0; g < 4; ++g) {
            int n = g * 4 + c;
            gate[g] = part[b * 16 + n] + part[1024 + b * 16 + n] + __ldg(&gp[g * 512 + hc]);
        }
        float i2 = sigf(gate[0]);
        float f2 = sigf(gate[1]);
        float g2 = tanhf(gate[2]);
        float o2 = sigf(gate[3]);
        cs = f2 * cs + i2 * g2;
        float h2 = o2 * tanhf(cs);

        __nv_bfloat16 hh, hl;
        split2(h2, hh, hl);
        size_t hidx = ((size_t)b * (Tt - 1) + (t - 1)) * Hh + hc;
        hallhi[hidx] = hh;
        halllo[hidx] = hl;

        if (t < Tt - 1) {
            hhiG[b * Hh + hc] = hh;
            hloG[b * Hh + hc] = hl;
            grid_barrier();
        }
    }
}

// ----------------------------------------------------------------- launch
extern "C" void kernel_launch(void* const* d_in, const int* in_sizes, int n_in,
                              void* d_out, int out_size) {
    const float* feat = (const float*)d_in[0];
    const float* emb = (const float*)d_in[1];
    const float* W_ih = (const float*)d_in[2];
    const float* W_hh = (const float*)d_in[3];
    const float* b_ih = (const float*)d_in[4];
    const float* b_hh = (const float*)d_in[5];
    const float* W_lin = (const float*)d_in[6];
    const float* b_lin = (const float*)d_in[7];
    float* out = (float*)d_out;

    float* gpre;
    __nv_bfloat16 *Xhi, *Xlo, *Wihhi, *Wihlo, *Wlhi, *Wllo, *hallhi, *halllo, *hhi, *hlo;
    cudaGetSymbolAddress((void**)&gpre, d_gpre);
    cudaGetSymbolAddress((void**)&Xhi, d_Xhi);
    cudaGetSymbolAddress((void**)&Xlo, d_Xlo);
    cudaGetSymbolAddress((void**)&Wihhi, d_Wihhi);
    cudaGetSymbolAddress((void**)&Wihlo, d_Wihlo);
    cudaGetSymbolAddress((void**)&Wlhi, d_Wlhi);
    cudaGetSymbolAddress((void**)&Wllo, d_Wllo);
    cudaGetSymbolAddress((void**)&hallhi, d_hallhi);
    cudaGetSymbolAddress((void**)&halllo, d_halllo);
    cudaGetSymbolAddress((void**)&hhi, d_hhi);
    cudaGetSymbolAddress((void**)&hlo, d_hlo);

    // Idempotent (no static guards allowed)
    cudaFuncSetAttribute(lstm_recurrence, cudaFuncAttributeMaxDynamicSharedMemorySize,
                         REC_SMEM_BYTES);
    cudaFuncSetAttribute(gemm_bf16x3, cudaFuncAttributeMaxDynamicSharedMemorySize,
                         GEMM_SMEM_BYTES);

    // 1) gather + split X; split weights
    build_x<<<(Tt * Bb * Ee + 255) / 256, 256>>>(feat, emb);
    split_bf16<<<(G4 * Kk + 255) / 256, 256>>>(W_ih, Wihhi, Wihlo, G4 * Kk);
    split_bf16<<<(Vv * Kk + 255) / 256, 256>>>(W_lin, Wlhi, Wllo, Vv * Kk);

    // 2) precompute gpre = X @ W_ih^T + b_ih + b_hh
    {
        dim3 grid(G4 / 128, (Tt * Bb + 127) / 128);  // 16 x 11
        gemm_bf16x3<<<grid, 256, GEMM_SMEM_BYTES>>>(Xhi, Xlo, Wihhi, Wihlo, b_ih, b_hh,
                                                    gpre, Tt * Bb, G4, Kk);
    }

    // 3) recurrence (persistent, tensor-core step GEMM)
    lstm_recurrence<<<REC_CTAS, 256, REC_SMEM_BYTES>>>(W_hh, gpre, hhi, hlo, hallhi,
                                                       halllo);

    // 4) projection: out[1280,10000] = hall @ W_lin^T + b_lin
    {
        dim3 grid((Vv + 127) / 128, ((Tt - 1) * Bb) / 128);  // 79 x 10
        gemm_bf16x3<<<grid, 256, GEMM_SMEM_BYTES>>>(hallhi, halllo, Wlhi, Wllo, b_lin,
                                                    nullptr, out, (Tt - 1) * Bb, Vv, Kk);
    }
}